// round 10
// baseline (speedup 1.0000x reference)
#include <cuda_runtime.h>

#define Tv 512
#define ROWW 60    // floats per emission smem row (56 data + 4 pad) -> 240B
#define MROWW 12   // ints per label/mask smem row (8 + 4 pad)
#define EFLOATS (64 * ROWW)
#define MINTS   (64 * MROWW)

#define OFF_ES   0
#define SZ_ES    (2 * 3 * EFLOATS * 4)
#define OFF_MS   (OFF_ES + SZ_ES)
#define SZ_MS    (2 * 3 * MINTS * 4)
#define OFF_LS   (OFF_MS + SZ_MS)
#define SZ_LS    (2 * 3 * MINTS * 4)
#define OFF_APUB (OFF_LS + SZ_LS)
#define OFF_BPUB (OFF_APUB + 64 * 8 * 4)
#define OFF_AX   (OFF_BPUB + 64 * 8 * 4)
#define OFF_BX   (OFF_AX + 256)
#define OFF_NUMF (OFF_BX + 256)
#define OFF_NUMB (OFF_NUMF + 256)
#define OFF_CF   (OFF_NUMB + 256)
#define OFF_CB   (OFF_CF + 256)
#define OFF_STR  (OFF_CB + 256)
#define SMEM_BYTES (OFF_STR + 256)

typedef unsigned long long u64;

static __device__ __forceinline__ u64 PK(float a, float b) {
    u64 r; asm("mov.b64 %0,{%1,%2};" : "=l"(r) : "r"(__float_as_uint(a)), "r"(__float_as_uint(b))); return r;
}
static __device__ __forceinline__ void UPK(u64 v, float& a, float& b) {
    unsigned x, y; asm("mov.b64 {%0,%1},%2;" : "=r"(x), "=r"(y) : "l"(v));
    a = __uint_as_float(x); b = __uint_as_float(y);
}
static __device__ __forceinline__ u64 FMA2(u64 a, u64 b, u64 c) {
    u64 d; asm("fma.rn.f32x2 %0,%1,%2,%3;" : "=l"(d) : "l"(a), "l"(b), "l"(c)); return d;
}
static __device__ __forceinline__ u64 MUL2(u64 a, u64 b) {
    u64 d; asm("mul.rn.f32x2 %0,%1,%2;" : "=l"(d) : "l"(a), "l"(b)); return d;
}
static __device__ __forceinline__ void cpa16(void* dst, const void* src) {
    unsigned d = (unsigned)__cvta_generic_to_shared(dst);
    asm volatile("cp.async.cg.shared.global [%0], [%1], 16;" :: "r"(d), "l"(src));
}
#define CP_COMMIT() asm volatile("cp.async.commit_group;")
#define CP_WAIT2()  asm volatile("cp.async.wait_group 2;")

__global__ void __launch_bounds__(64, 1)
crf_kernel(const float* __restrict__ em,
           const int* __restrict__ labels,
           const int* __restrict__ mask,
           const float* __restrict__ startT,
           const float* __restrict__ endT,
           const float* __restrict__ trans,
           float* __restrict__ out)
{
    extern __shared__ char sb[];
    float* STR = (float*)(sb + OFF_STR);

    const int tid  = threadIdx.x;
    const int wid  = tid >> 5;
    const int lane = tid & 31;

    for (int i = tid; i < 49; i += 64) STR[i] = trans[i];
    __syncthreads();

    const int base = blockIdx.x * 64;
    const float* emb  = em + (size_t)base * (Tv * 7);
    const int*   labb = labels + (size_t)base * Tv;
    const int*   mskb = mask   + (size_t)base * Tv;

    u64 EE[7][7];
#pragma unroll
    for (int i = 0; i < 7; i++)
#pragma unroll
        for (int j = 0; j < 7; j++) {
            float e = __expf(__ldg(&trans[i * 7 + j]));
            EE[i][j] = PK(e, e);
        }

    float* ESW = (float*)(sb + OFF_ES) + wid * 3 * EFLOATS;
    int*   MSW = (int*)(sb + OFF_MS) + wid * 3 * MINTS;
    int*   LSW = (int*)(sb + OFF_LS) + wid * 3 * MINTS;

#define STAGE(SLOT, MM) do { \
    float* _eb = ESW + (SLOT) * EFLOATS; \
    int*   _mb = MSW + (SLOT) * MINTS; \
    int*   _lb = LSW + (SLOT) * MINTS; \
    _Pragma("unroll") \
    for (int i = 0; i < 28; i++) { \
        int idx = i * 32 + lane; int r = (idx * 4682) >> 16; int c = idx - r * 14; \
        cpa16(_eb + r * ROWW + c * 4, emb + (size_t)r * (Tv * 7) + (MM) * 56 + c * 4); \
    } \
    _Pragma("unroll") \
    for (int i = 0; i < 4; i++) { \
        int idx = i * 32 + lane; int s = idx >> 1; int h = idx & 1; \
        cpa16(_mb + s * MROWW + h * 4, mskb + (size_t)s * Tv + (MM) * 8 + h * 4); \
        cpa16(_lb + s * MROWW + h * 4, labb + (size_t)s * Tv + (MM) * 8 + h * 4); \
    } \
    CP_COMMIT(); } while (0)

    u64 p[7];
    int xsA = 0, xsB = 0;
    float numP = 0.f, numQ = 0.f;
    int   cntP = 0,   cntQ = 0;

#define RENORM() do { \
    float aA[7], aB[7]; \
    _Pragma("unroll") for (int j = 0; j < 7; j++) UPK(p[j], aA[j], aB[j]); \
    float mxA = aA[0], mxB = aB[0]; \
    _Pragma("unroll") for (int j = 1; j < 7; j++) { mxA = fmaxf(mxA, aA[j]); mxB = fmaxf(mxB, aB[j]); } \
    int exA = (__float_as_int(mxA) >> 23) & 0xFF; \
    int exB = (__float_as_int(mxB) >> 23) & 0xFF; \
    float invA = __int_as_float((254 - exA) << 23); \
    float invB = __int_as_float((254 - exB) << 23); \
    xsA += exA - 127; xsB += exB - 127; \
    u64 iv = PK(invA, invB); \
    _Pragma("unroll") for (int j = 0; j < 7; j++) p[j] = MUL2(p[j], iv); } while (0)

    // transient all-mask check: load, reduce, discard
#define ALLMASK(mrA, mrB, dst) do { \
    int4 _a0 = *(const int4*)(mrA), _a1 = *(const int4*)((mrA) + 4); \
    int4 _b0 = *(const int4*)(mrB), _b1 = *(const int4*)((mrB) + 4); \
    int _am = _a0.x&_a0.y&_a0.z&_a0.w&_a1.x&_a1.y&_a1.z&_a1.w \
            & _b0.x&_b0.y&_b0.z&_b0.w&_b1.x&_b1.y&_b1.z&_b1.w; \
    dst = __all_sync(0xFFFFFFFFu, _am); } while (0)

    if (wid == 0) {
        // ======================= FORWARD: t in [0,256) =======================
        auto FSTEP = [&](const float* eA, const float* eB) {
            u64 q[7];
#pragma unroll
            for (int j = 0; j < 7; j++) q[j] = MUL2(p[0], EE[0][j]);
#pragma unroll
            for (int i = 1; i < 7; i++)
#pragma unroll
                for (int j = 0; j < 7; j++) q[j] = FMA2(p[i], EE[i][j], q[j]);
#pragma unroll
            for (int j = 0; j < 7; j++)
                p[j] = MUL2(q[j], PK(__expf(eA[j]), __expf(eB[j])));
        };
        auto SSTEP = [&](const float* eA, const float* eB, int MA, int MB) {
            u64 q[7];
#pragma unroll
            for (int j = 0; j < 7; j++) q[j] = MUL2(p[0], EE[0][j]);
#pragma unroll
            for (int i = 1; i < 7; i++)
#pragma unroll
                for (int j = 0; j < 7; j++) q[j] = FMA2(p[i], EE[i][j], q[j]);
#pragma unroll
            for (int j = 0; j < 7; j++)
                q[j] = MUL2(q[j], PK(__expf(eA[j]), __expf(eB[j])));
            u64 mm = ((u64)(MB ? 0xFFFFFFFFu : 0u) << 32) | (MA ? 0xFFFFFFFFu : 0u);
#pragma unroll
            for (int j = 0; j < 7; j++) p[j] = (q[j] & mm) | (p[j] & ~mm);
        };

        STAGE(0, 0); STAGE(1, 1); STAGE(2, 2);
        CP_WAIT2(); __syncwarp();

        int carryA = 0, carryB = 0;
#pragma unroll 1
        for (int m = 0; m < 32; m++) {
            int st = m % 3;
            const float* rA = ESW + st * EFLOATS + lane * ROWW;
            const float* rB = rA + 32 * ROWW;
            const int* mrA = MSW + st * MINTS + lane * MROWW;
            const int* mrB = mrA + 32 * MROWW;
            const int* lrA = LSW + st * MINTS + lane * MROWW;
            const int* lrB = lrA + 32 * MROWW;

            int fast; ALLMASK(mrA, mrB, fast);

            // ---- numerator (prev = raw adjacent label, carried scalar) ----
            int PA = carryA, PB = carryB;
#pragma unroll
            for (int s = 0; s < 8; s++) {
                int LA = lrA[s]; LA = LA < 0 ? 0 : LA;
                int LB = lrB[s]; LB = LB < 0 ? 0 : LB;
                if (m == 0 && s == 0) {
                    numP += __ldg(startT + LA) + rA[LA];
                    numQ += __ldg(startT + LB) + rB[LB];
                    cntP++; cntQ++;
                } else if (fast) {
                    numP += STR[PA * 7 + LA] + rA[s * 7 + LA];
                    numQ += STR[PB * 7 + LB] + rB[s * 7 + LB];
                    cntP++; cntQ++;
                } else {
                    int MA = mrA[s], MB = mrB[s];
                    float vA = STR[PA * 7 + LA] + rA[s * 7 + LA];
                    float vB = STR[PB * 7 + LB] + rB[s * 7 + LB];
                    numP += MA ? vA : 0.f;  cntP += MA ? 1 : 0;
                    numQ += MB ? vB : 0.f;  cntQ += MB ? 1 : 0;
                }
                PA = LA; PB = LB;
            }
            carryA = PA; carryB = PB;

            // ---- recursion ----
            if (m == 0) {
                float qA[7], qB[7];
#pragma unroll
                for (int j = 0; j < 7; j++) {
                    float s0 = __ldg(startT + j);
                    qA[j] = __expf(s0 + rA[j]);
                    qB[j] = __expf(s0 + rB[j]);
                }
                float mxA = qA[0], mxB = qB[0];
#pragma unroll
                for (int j = 1; j < 7; j++) { mxA = fmaxf(mxA, qA[j]); mxB = fmaxf(mxB, qB[j]); }
                int exA = (__float_as_int(mxA) >> 23) & 0xFF;
                int exB = (__float_as_int(mxB) >> 23) & 0xFF;
                float invA = __int_as_float((254 - exA) << 23);
                float invB = __int_as_float((254 - exB) << 23);
                xsA = exA - 127; xsB = exB - 127;
#pragma unroll
                for (int j = 0; j < 7; j++) p[j] = PK(qA[j] * invA, qB[j] * invB);
#pragma unroll
                for (int s = 1; s < 8; s++) SSTEP(rA + s * 7, rB + s * 7, mrA[s], mrB[s]);
            } else if (fast) {
#pragma unroll
                for (int s = 0; s < 8; s++) FSTEP(rA + s * 7, rB + s * 7);
            } else {
#pragma unroll
                for (int s = 0; s < 8; s++) SSTEP(rA + s * 7, rB + s * 7, mrA[s], mrB[s]);
            }
            RENORM();
            __syncwarp();
            if (m + 3 < 32) STAGE((m + 3) % 3, m + 3); else CP_COMMIT();
        }

        // ---- publish alpha ----
        {
            float aA[7], aB[7];
#pragma unroll
            for (int j = 0; j < 7; j++) UPK(p[j], aA[j], aB[j]);
            float* AP = (float*)(sb + OFF_APUB);
            int*   AX = (int*)(sb + OFF_AX);
            float* NF = (float*)(sb + OFF_NUMF);
            int*   CF = (int*)(sb + OFF_CF);
#pragma unroll
            for (int j = 0; j < 7; j++) { AP[lane * 8 + j] = aA[j]; AP[(lane + 32) * 8 + j] = aB[j]; }
            AX[lane] = xsA; AX[lane + 32] = xsB;
            NF[lane] = numP; NF[lane + 32] = numQ;
            CF[lane] = cntP; CF[lane + 32] = cntQ;
        }
        __syncthreads();

        // ---- combine ----
        {
            const float* AP = (const float*)(sb + OFF_APUB);
            const int*   AX = (const int*)(sb + OFF_AX);
            const float* NF = (const float*)(sb + OFF_NUMF);
            const int*   CF = (const int*)(sb + OFF_CF);
            const float* BP = (const float*)(sb + OFF_BPUB);
            const int*   BX = (const int*)(sb + OFF_BX);
            const float* NB = (const float*)(sb + OFF_NUMB);
            const int*   CB = (const int*)(sb + OFF_CB);
            const float LN2 = 0.69314718055994531f;
            float r = 0.f;
#pragma unroll
            for (int k = 0; k < 2; k++) {
                int seq = lane + k * 32;
                float acc = 0.f;
#pragma unroll
                for (int j = 0; j < 7; j++) acc = fmaf(AP[seq * 8 + j], BP[seq * 8 + j], acc);
                float den = __logf(acc) + (float)(AX[seq] + BX[seq]) * LN2;
                int cnt = CF[seq] + CB[seq];
                int lastIdx = cnt > 0 ? cnt - 1 : Tv - 1;
                int lt = __ldg(labb + (size_t)seq * Tv + lastIdx);
                lt = lt < 0 ? 0 : lt;
                float num = NF[seq] + NB[seq] + __ldg(endT + lt);
                r += den - num;
            }
#pragma unroll
            for (int off = 16; off > 0; off >>= 1)
                r += __shfl_xor_sync(0xFFFFFFFFu, r, off);
            if (lane == 0) atomicAdd(out, r);
        }

    } else {
        // ======================= BACKWARD: t in [256,512) =======================
        auto BFSTEP = [&](const float* eA, const float* eB) {
            u64 w[7];
#pragma unroll
            for (int j = 0; j < 7; j++)
                w[j] = MUL2(p[j], PK(__expf(eA[j]), __expf(eB[j])));
            u64 q[7];
#pragma unroll
            for (int i = 0; i < 7; i++) q[i] = MUL2(w[0], EE[i][0]);
#pragma unroll
            for (int j = 1; j < 7; j++)
#pragma unroll
                for (int i = 0; i < 7; i++) q[i] = FMA2(w[j], EE[i][j], q[i]);
#pragma unroll
            for (int i = 0; i < 7; i++) p[i] = q[i];
        };
        auto BSSTEP = [&](const float* eA, const float* eB, int MA, int MB) {
            u64 w[7];
#pragma unroll
            for (int j = 0; j < 7; j++)
                w[j] = MUL2(p[j], PK(__expf(eA[j]), __expf(eB[j])));
            u64 q[7];
#pragma unroll
            for (int i = 0; i < 7; i++) q[i] = MUL2(w[0], EE[i][0]);
#pragma unroll
            for (int j = 1; j < 7; j++)
#pragma unroll
                for (int i = 0; i < 7; i++) q[i] = FMA2(w[j], EE[i][j], q[i]);
            u64 mm = ((u64)(MB ? 0xFFFFFFFFu : 0u) << 32) | (MA ? 0xFFFFFFFFu : 0u);
#pragma unroll
            for (int i = 0; i < 7; i++) p[i] = (q[i] & mm) | (p[i] & ~mm);
        };

        int L255A = __ldg(labb + (size_t)lane * Tv + 255);
        int L255B = __ldg(labb + (size_t)(lane + 32) * Tv + 255);
        L255A = L255A < 0 ? 0 : L255A;
        L255B = L255B < 0 ? 0 : L255B;

#pragma unroll
        for (int j = 0; j < 7; j++) { float e = __expf(__ldg(endT + j)); p[j] = PK(e, e); }

        STAGE(0, 63); STAGE(1, 62); STAGE(2, 61);
        CP_WAIT2(); __syncwarp();

        int pendLA = 0, pendMA = 0, pendLB = 0, pendMB = 0;
#pragma unroll 1
        for (int k = 0; k < 32; k++) {
            int st = k % 3;
            const float* rA = ESW + st * EFLOATS + lane * ROWW;
            const float* rB = rA + 32 * ROWW;
            const int* mrA = MSW + st * MINTS + lane * MROWW;
            const int* mrB = mrA + 32 * MROWW;
            const int* lrA = LSW + st * MINTS + lane * MROWW;
            const int* lrB = lrA + 32 * MROWW;

            int fast; ALLMASK(mrA, mrB, fast);

            // ---- numerator: internal pairs s=1..7 (prev carried) ----
            int PA = lrA[0]; PA = PA < 0 ? 0 : PA;
            int PB = lrB[0]; PB = PB < 0 ? 0 : PB;
            int L0A = PA, L0B = PB;
#pragma unroll
            for (int s = 1; s < 8; s++) {
                int LA = lrA[s]; LA = LA < 0 ? 0 : LA;
                int LB = lrB[s]; LB = LB < 0 ? 0 : LB;
                if (fast) {
                    numP += STR[PA * 7 + LA] + rA[s * 7 + LA];
                    numQ += STR[PB * 7 + LB] + rB[s * 7 + LB];
                    cntP++; cntQ++;
                } else {
                    int MA = mrA[s], MB = mrB[s];
                    float vA = STR[PA * 7 + LA] + rA[s * 7 + LA];
                    float vB = STR[PB * 7 + LB] + rB[s * 7 + LB];
                    numP += MA ? vA : 0.f;  cntP += MA ? 1 : 0;
                    numQ += MB ? vB : 0.f;  cntQ += MB ? 1 : 0;
                }
                PA = LA; PB = LB;
            }
            // close pending cross term (uses this macro's last label = PA/PB)
            numP += pendMA ? STR[PA * 7 + pendLA] : 0.f;
            numQ += pendMB ? STR[PB * 7 + pendLB] : 0.f;
            // s=0: emission now, trans pends
            {
                int M0A = fast ? 1 : mrA[0];
                int M0B = fast ? 1 : mrB[0];
                numP += M0A ? rA[L0A] : 0.f;  cntP += M0A ? 1 : 0;
                numQ += M0B ? rB[L0B] : 0.f;  cntQ += M0B ? 1 : 0;
                pendLA = L0A; pendMA = M0A;
                pendLB = L0B; pendMB = M0B;
            }

            // ---- recursion (descending) ----
            if (fast) {
#pragma unroll
                for (int s = 7; s >= 0; s--) BFSTEP(rA + s * 7, rB + s * 7);
            } else {
#pragma unroll
                for (int s = 7; s >= 0; s--) BSSTEP(rA + s * 7, rB + s * 7, mrA[s], mrB[s]);
            }
            RENORM();
            __syncwarp();
            if (k + 3 < 32) STAGE((k + 3) % 3, 63 - (k + 3)); else CP_COMMIT();
        }

        numP += pendMA ? STR[L255A * 7 + pendLA] : 0.f;
        numQ += pendMB ? STR[L255B * 7 + pendLB] : 0.f;

        // ---- publish beta ----
        {
            float aA[7], aB[7];
#pragma unroll
            for (int j = 0; j < 7; j++) UPK(p[j], aA[j], aB[j]);
            float* BP = (float*)(sb + OFF_BPUB);
            int*   BX = (int*)(sb + OFF_BX);
            float* NB = (float*)(sb + OFF_NUMB);
            int*   CB = (int*)(sb + OFF_CB);
#pragma unroll
            for (int j = 0; j < 7; j++) { BP[lane * 8 + j] = aA[j]; BP[(lane + 32) * 8 + j] = aB[j]; }
            BX[lane] = xsA; BX[lane + 32] = xsB;
            NB[lane] = numP; NB[lane + 32] = numQ;
            CB[lane] = cntP; CB[lane + 32] = cntQ;
        }
        __syncthreads();
    }

#undef STAGE
#undef RENORM
#undef ALLMASK
}

extern "C" void kernel_launch(void* const* d_in, const int* in_sizes, int n_in,
                              void* d_out, int out_size)
{
    const float* em     = (const float*)d_in[0];
    const int*   labels = (const int*)  d_in[1];
    const int*   mask   = (const int*)  d_in[2];
    const float* startT = (const float*)d_in[3];
    const float* endT   = (const float*)d_in[4];
    const float* trans  = (const float*)d_in[5];

    cudaFuncSetAttribute(crf_kernel, cudaFuncAttributeMaxDynamicSharedMemorySize, SMEM_BYTES);
    cudaMemsetAsync(d_out, 0, sizeof(float));
    crf_kernel<<<128, 64, SMEM_BYTES>>>(em, labels, mask, startT, endT, trans, (float*)d_out);
}

// round 11
// speedup vs baseline: 1.9702x; 1.9702x over previous
#include <cuda_runtime.h>

#define Tv 512
#define ROWW 60                 // 56 data + 4 pad floats per seq row (240B)
#define STAGEF (32 * ROWW)

__device__ float gA[8192 * 8];
__device__ float gU[8192 * 8];
__device__ int   gXF[8192], gXB[8192];
__device__ float gNF[8192], gNB[8192];
__device__ int   gCF[8192], gCB[8192];

static __device__ __forceinline__ void cpa16(void* dst, const void* src) {
    unsigned d = (unsigned)__cvta_generic_to_shared(dst);
    asm volatile("cp.async.cg.shared.global [%0], [%1], 16;" :: "r"(d), "l"(src));
}
#define CP_COMMIT() asm volatile("cp.async.commit_group;")
#define CP_WAIT2()  asm volatile("cp.async.wait_group 2;")

__global__ void __launch_bounds__(32, 1)
crf_half_kernel(const float* __restrict__ em,
                const int* __restrict__ labels,
                const int* __restrict__ mask,
                const float* __restrict__ startT,
                const float* __restrict__ endT,
                const float* __restrict__ trans)
{
    __shared__ float ES[3 * STAGEF];
    __shared__ float STRs[49];

    const int lane  = threadIdx.x;
    const int half  = blockIdx.x >> 8;       // 0 = forward, 1 = backward
    const int group = blockIdx.x & 255;
    const int seq   = group * 32 + lane;

    const float* emb = em + (size_t)(group * 32) * (Tv * 7);
    const int4* lb4 = (const int4*)(labels + (size_t)seq * Tv);
    const int4* mb4 = (const int4*)(mask   + (size_t)seq * Tv);

    for (int i = lane; i < 49; i += 32) STRs[i] = trans[i];
    __syncwarp();

    float E[7][7];
#pragma unroll
    for (int i = 0; i < 7; i++)
#pragma unroll
        for (int j = 0; j < 7; j++)
            E[i][j] = __expf(__ldg(&trans[i * 7 + j]));

#define STAGE(SLOT, MM) do { \
    float* _d = ES + (SLOT) * STAGEF; \
    _Pragma("unroll") \
    for (int i = 0; i < 14; i++) { \
        int idx = i * 32 + lane; int r = (idx * 4682) >> 16; int c = idx - r * 14; \
        cpa16(_d + r * ROWW + c * 4, emb + (size_t)r * (Tv * 7) + (MM) * 56 + c * 4); \
    } \
    CP_COMMIT(); } while (0)

    float st[7];
    float num = 0.f;
    int cnt = 0, xs = 0;

#define RENORM() do { \
    float mx = st[0]; \
    _Pragma("unroll") for (int j = 1; j < 7; j++) mx = fmaxf(mx, st[j]); \
    int ex = (__float_as_int(mx) >> 23) & 0xFF; \
    float inv = __int_as_float((254 - ex) << 23); \
    xs += ex - 127; \
    _Pragma("unroll") for (int j = 0; j < 7; j++) st[j] *= inv; } while (0)

    if (half == 0) {
        // ======================= FORWARD: t in [0,256) =======================
        auto FST = [&](const float* e) {
            float q[7];
#pragma unroll
            for (int j = 0; j < 7; j++) q[j] = st[0] * E[0][j];
#pragma unroll
            for (int i = 1; i < 7; i++)
#pragma unroll
                for (int j = 0; j < 7; j++) q[j] = fmaf(st[i], E[i][j], q[j]);
#pragma unroll
            for (int j = 0; j < 7; j++) st[j] = q[j] * __expf(e[j]);
        };
        auto SST = [&](const float* e, int M) {
            float q[7];
#pragma unroll
            for (int j = 0; j < 7; j++) q[j] = st[0] * E[0][j];
#pragma unroll
            for (int i = 1; i < 7; i++)
#pragma unroll
                for (int j = 0; j < 7; j++) q[j] = fmaf(st[i], E[i][j], q[j]);
#pragma unroll
            for (int j = 0; j < 7; j++) {
                float v = q[j] * __expf(e[j]);
                st[j] = M ? v : st[j];
            }
        };

        STAGE(0, 0); STAGE(1, 1); STAGE(2, 2);
        int4 lc0 = __ldg(lb4 + 0), lc1 = __ldg(lb4 + 1);
        int4 mc0 = __ldg(mb4 + 0), mc1 = __ldg(mb4 + 1);
        CP_WAIT2(); __syncwarp();

        int carry;
        // ---- macro 0 (peeled): init t=0, steps 1..7 ----
        {
            const float* r = ES + lane * ROWW;
            int la[8] = {lc0.x, lc0.y, lc0.z, lc0.w, lc1.x, lc1.y, lc1.z, lc1.w};
            int ma[8] = {mc0.x, mc0.y, mc0.z, mc0.w, mc1.x, mc1.y, mc1.z, mc1.w};
            lc0 = __ldg(lb4 + 2); lc1 = __ldg(lb4 + 3);
            mc0 = __ldg(mb4 + 2); mc1 = __ldg(mb4 + 3);

            int prevL = 0;
#pragma unroll
            for (int s = 0; s < 8; s++) {
                int L = la[s] < 0 ? 0 : la[s];
                if (s == 0) {
                    num = __ldg(startT + L) + r[L];
                } else {
                    float v = STRs[prevL * 7 + L] + r[s * 7 + L];
                    num += ma[s] ? v : 0.f;
                }
                cnt += ma[s] ? 1 : 0;
                prevL = L;
            }
            carry = prevL;

#pragma unroll
            for (int j = 0; j < 7; j++) st[j] = __expf(__ldg(startT + j) + r[j]);
            RENORM();
#pragma unroll
            for (int s = 1; s < 8; s++) SST(r + s * 7, ma[s]);
            RENORM();
            __syncwarp();
            STAGE(0, 3);
        }

#pragma unroll 1
        for (int m = 1; m < 32; m++) {
            CP_WAIT2(); __syncwarp();
            const float* r = ES + (m % 3) * STAGEF + lane * ROWW;
            int la[8] = {lc0.x, lc0.y, lc0.z, lc0.w, lc1.x, lc1.y, lc1.z, lc1.w};
            int ma[8] = {mc0.x, mc0.y, mc0.z, mc0.w, mc1.x, mc1.y, mc1.z, mc1.w};
            if (m < 31) {
                lc0 = __ldg(lb4 + 2 * m + 2); lc1 = __ldg(lb4 + 2 * m + 3);
                mc0 = __ldg(mb4 + 2 * m + 2); mc1 = __ldg(mb4 + 2 * m + 3);
            }

            int prevL = carry;
#pragma unroll
            for (int s = 0; s < 8; s++) {
                int L = la[s] < 0 ? 0 : la[s];
                float v = STRs[prevL * 7 + L] + r[s * 7 + L];
                num += ma[s] ? v : 0.f;
                cnt += ma[s] ? 1 : 0;
                prevL = L;
            }
            carry = prevL;

            int am = ma[0] & ma[1] & ma[2] & ma[3] & ma[4] & ma[5] & ma[6] & ma[7];
            if (__all_sync(0xFFFFFFFFu, am)) {
#pragma unroll
                for (int s = 0; s < 8; s++) FST(r + s * 7);
            } else {
#pragma unroll
                for (int s = 0; s < 8; s++) SST(r + s * 7, ma[s]);
            }
            RENORM();
            __syncwarp();
            if (m + 3 < 32) STAGE((m + 3) % 3, m + 3); else CP_COMMIT();
        }

#pragma unroll
        for (int j = 0; j < 7; j++) gA[seq * 8 + j] = st[j];
        gXF[seq] = xs; gNF[seq] = num; gCF[seq] = cnt;

    } else {
        // ======================= BACKWARD: t in [256,512) =======================
        auto BFST = [&](const float* e) {
            float w[7];
#pragma unroll
            for (int j = 0; j < 7; j++) w[j] = st[j] * __expf(e[j]);
            float q[7];
#pragma unroll
            for (int i = 0; i < 7; i++) q[i] = w[0] * E[i][0];
#pragma unroll
            for (int j = 1; j < 7; j++)
#pragma unroll
                for (int i = 0; i < 7; i++) q[i] = fmaf(w[j], E[i][j], q[i]);
#pragma unroll
            for (int i = 0; i < 7; i++) st[i] = q[i];
        };
        auto BSST = [&](const float* e, int M) {
            float w[7];
#pragma unroll
            for (int j = 0; j < 7; j++) w[j] = st[j] * __expf(e[j]);
            float q[7];
#pragma unroll
            for (int i = 0; i < 7; i++) q[i] = w[0] * E[i][0];
#pragma unroll
            for (int j = 1; j < 7; j++)
#pragma unroll
                for (int i = 0; i < 7; i++) q[i] = fmaf(w[j], E[i][j], q[i]);
#pragma unroll
            for (int i = 0; i < 7; i++) st[i] = M ? q[i] : st[i];
        };

        STAGE(0, 63); STAGE(1, 62); STAGE(2, 61);
        int4 lc0 = __ldg(lb4 + 126), lc1 = __ldg(lb4 + 127);
        int4 mc0 = __ldg(mb4 + 126), mc1 = __ldg(mb4 + 127);

#pragma unroll
        for (int j = 0; j < 7; j++) st[j] = __expf(__ldg(endT + j));

        CP_WAIT2(); __syncwarp();

        int pendL = 0, pendM = 0;
#pragma unroll 1
        for (int k = 0; k < 32; k++) {
            if (k > 0) { CP_WAIT2(); __syncwarp(); }
            const float* r = ES + (k % 3) * STAGEF + lane * ROWW;
            int la[8] = {lc0.x, lc0.y, lc0.z, lc0.w, lc1.x, lc1.y, lc1.z, lc1.w};
            int ma[8] = {mc0.x, mc0.y, mc0.z, mc0.w, mc1.x, mc1.y, mc1.z, mc1.w};
            if (k < 31) {
                int nm = 63 - k - 1;
                lc0 = __ldg(lb4 + 2 * nm);     lc1 = __ldg(lb4 + 2 * nm + 1);
                mc0 = __ldg(mb4 + 2 * nm);     mc1 = __ldg(mb4 + 2 * nm + 1);
            }

            // ---- numerator for this macro's times (chain-free) ----
            int L0 = la[0] < 0 ? 0 : la[0];
            int P = L0;
#pragma unroll
            for (int s = 1; s < 8; s++) {
                int L = la[s] < 0 ? 0 : la[s];
                float v = STRs[P * 7 + L] + r[s * 7 + L];
                num += ma[s] ? v : 0.f;
                cnt += ma[s] ? 1 : 0;
                P = L;
            }
            // close pending cross-macro trans term with this macro's last label (P)
            num += pendM ? STRs[P * 7 + pendL] : 0.f;
            // s=0: emission now; its trans term pends on the next (earlier) macro
            num += ma[0] ? r[L0] : 0.f;
            cnt += ma[0] ? 1 : 0;
            pendL = L0; pendM = ma[0];

            // ---- recursion, descending time ----
            int am = ma[0] & ma[1] & ma[2] & ma[3] & ma[4] & ma[5] & ma[6] & ma[7];
            if (__all_sync(0xFFFFFFFFu, am)) {
#pragma unroll
                for (int s = 7; s >= 0; s--) BFST(r + s * 7);
            } else {
#pragma unroll
                for (int s = 7; s >= 0; s--) BSST(r + s * 7, ma[s]);
            }
            RENORM();
            __syncwarp();
            if (k + 3 < 32) STAGE((k + 3) % 3, 63 - (k + 3)); else CP_COMMIT();
        }

        // close final pending term against label t=255
        int L255 = __ldg(labels + (size_t)seq * Tv + 255);
        L255 = L255 < 0 ? 0 : L255;
        num += pendM ? STRs[L255 * 7 + pendL] : 0.f;

#pragma unroll
        for (int j = 0; j < 7; j++) gU[seq * 8 + j] = st[j];
        gXB[seq] = xs; gNB[seq] = num; gCB[seq] = cnt;
    }

#undef STAGE
#undef RENORM
}

__global__ void __launch_bounds__(256)
combine_kernel(const int* __restrict__ labels,
               const float* __restrict__ endT,
               float* __restrict__ out)
{
    const int seq = blockIdx.x * 256 + threadIdx.x;
    float acc = 0.f;
#pragma unroll
    for (int j = 0; j < 7; j++) acc = fmaf(gA[seq * 8 + j], gU[seq * 8 + j], acc);
    float den = __logf(acc) + (float)(gXF[seq] + gXB[seq]) * 0.69314718055994531f;

    int c = gCF[seq] + gCB[seq];
    int li = c > 0 ? c - 1 : 0;
    int lt = __ldg(labels + (size_t)seq * Tv + li);
    lt = lt < 0 ? 0 : lt;
    float num = gNF[seq] + gNB[seq] + __ldg(endT + lt);

    float v = den - num;
#pragma unroll
    for (int off = 16; off > 0; off >>= 1)
        v += __shfl_xor_sync(0xFFFFFFFFu, v, off);
    if ((threadIdx.x & 31) == 0) atomicAdd(out, v);
}

extern "C" void kernel_launch(void* const* d_in, const int* in_sizes, int n_in,
                              void* d_out, int out_size)
{
    const float* em     = (const float*)d_in[0];
    const int*   labels = (const int*)  d_in[1];
    const int*   mask   = (const int*)  d_in[2];
    const float* startT = (const float*)d_in[3];
    const float* endT   = (const float*)d_in[4];
    const float* trans  = (const float*)d_in[5];

    cudaMemsetAsync(d_out, 0, sizeof(float));
    crf_half_kernel<<<512, 32>>>(em, labels, mask, startT, endT, trans);
    combine_kernel<<<32, 256>>>(labels, endT, (float*)d_out);
}